// round 13
// baseline (speedup 1.0000x reference)
#include <cuda_runtime.h>
#include <cuda_bf16.h>
#include <cstdint>

#define D        64
#define EXPERTS  8
#define NTOK     (1 << 20)
#define SCAN_TPB 256
#define SCAN_TOKENS 4096
#define NUM_SCAN_CTAS (NTOK / SCAN_TOKENS)   // 256
#define TILE     128
#define GBLOCK   256
#define NCTA_GEMM 592

#if defined(__CUDA_ARCH_FEAT_SM103_ALL) || \
    (defined(__CUDA_ARCH_SPECIFIC__) && (__CUDA_ARCH_SPECIFIC__ == 1030))
#define TCGEN_OK 1
#else
#define TCGEN_OK 0
#endif

// idesc kind::f16: dtype F32(1<<4) | atype BF16(1<<7) | btype BF16(1<<10)
//                  | (N/8)<<17 | (M/16)<<24   => M=128,N=64
#define IDESC_BF16 0x8100490u

// smem offsets (base is 1KB-aligned)
#define OFF_BH   0        // B hi: 64 rows x 128B SW128
#define OFF_BL   8192     // B lo
#define OFF_BIAS 16384    // 64 floats
#define OFF_MBAR 16640    // 8B
#define OFF_TMEM 16648    // 4B
#define OFF_META 16656    // 25 ints
#define OFF_TICK 16756    // 1 int
#define SMEM_SZ  (16768 + 1024)

// TMEM columns: A hi [0,32), A lo [32,64), acc [64,128)
#define TM_AHI  0
#define TM_ALO  32
#define TM_ACC  64
#define TM_COLS 128

// ---------------- device scratch ----------------
__device__ int g_perm[NTOK];
__device__ int g_blockCnt[NUM_SCAN_CTAS * EXPERTS];
__device__ int g_blockBase[NUM_SCAN_CTAS * EXPERTS];
__device__ int g_cnt[EXPERTS];
__device__ int g_off[EXPERTS + 1];
__device__ int g_tileOfs[EXPERTS + 1];
__device__ int g_ticket;

// ---------------- helpers ----------------
__device__ __forceinline__ uint32_t smem_u32(const void* p) {
    uint32_t a;
    asm("{ .reg .u64 t; cvta.to.shared.u64 t, %1; cvt.u32.u64 %0, t; }"
        : "=r"(a) : "l"(p));
    return a;
}
__device__ __forceinline__ uint32_t bits2(__nv_bfloat162 h) {
    return *reinterpret_cast<uint32_t*>(&h);
}

#if TCGEN_OK
__device__ __forceinline__ uint32_t elect_one_pred() {
    uint32_t p;
    asm volatile("{\n\t.reg .pred p;\n\telect.sync _|p, 0xFFFFFFFF;\n\t"
                 "selp.b32 %0, 1, 0, p;\n\t}" : "=r"(p));
    return p;
}
__device__ __forceinline__ uint64_t make_desc(uint32_t addr) {
    // SW128 (layout 2), Blackwell version=1, SBO=64, LBO=1
    const uint64_t base = (2ull << 61) | (1ull << 46) | (64ull << 32) | (1ull << 16);
    return base | ((uint64_t)(addr >> 4) & 0x3FFF);
}
// TS form: A in TMEM
__device__ __forceinline__ void mma_f16_ts(uint32_t d_tmem, uint32_t a_tmem,
                                           uint64_t b_desc, uint32_t idesc,
                                           uint32_t accum) {
    asm volatile(
        "{\n\t.reg .pred p;\n\tsetp.ne.u32 p, %5, 0;\n\t"
        "tcgen05.mma.cta_group::1.kind::f16 [%0], [%1], %2, %3, {%4, %4, %4, %4}, p;\n\t}"
        :: "r"(d_tmem), "r"(a_tmem), "l"(b_desc), "r"(idesc), "r"(0u), "r"(accum)
        : "memory");
}
__device__ __forceinline__ void mbar_wait(uint32_t mbar, uint32_t parity) {
    asm volatile(
        "{\n\t.reg .pred P;\n\t"
        "WL_%=:\n\t"
        "mbarrier.try_wait.parity.acquire.cta.shared::cta.b64 P, [%0], %1, 0x989680;\n\t"
        "@P bra.uni WD_%=;\n\t"
        "bra.uni WL_%=;\n\t"
        "WD_%=:\n\t}"
        :: "r"(mbar), "r"(parity) : "memory");
}
#define TTM_ST_X16(addr, r) \
    asm volatile( \
        "tcgen05.st.sync.aligned.32x32b.x16.b32 [%0], " \
        "{%1, %2, %3, %4, %5, %6, %7, %8, " \
        " %9, %10, %11, %12, %13, %14, %15, %16};" \
        :: "r"(addr), \
           "r"((r)[0]),  "r"((r)[1]),  "r"((r)[2]),  "r"((r)[3]), \
           "r"((r)[4]),  "r"((r)[5]),  "r"((r)[6]),  "r"((r)[7]), \
           "r"((r)[8]),  "r"((r)[9]),  "r"((r)[10]), "r"((r)[11]), \
           "r"((r)[12]), "r"((r)[13]), "r"((r)[14]), "r"((r)[15]) \
        : "memory")
#define LDTM_X32(r, addr) \
    asm volatile( \
        "tcgen05.ld.sync.aligned.32x32b.x32.b32 " \
        "{%0, %1, %2, %3, %4, %5, %6, %7, " \
        " %8, %9, %10, %11, %12, %13, %14, %15, " \
        " %16, %17, %18, %19, %20, %21, %22, %23, " \
        " %24, %25, %26, %27, %28, %29, %30, %31}, [%32];" \
        : "=r"((r)[0]),  "=r"((r)[1]),  "=r"((r)[2]),  "=r"((r)[3]), \
          "=r"((r)[4]),  "=r"((r)[5]),  "=r"((r)[6]),  "=r"((r)[7]), \
          "=r"((r)[8]),  "=r"((r)[9]),  "=r"((r)[10]), "=r"((r)[11]), \
          "=r"((r)[12]), "=r"((r)[13]), "=r"((r)[14]), "=r"((r)[15]), \
          "=r"((r)[16]), "=r"((r)[17]), "=r"((r)[18]), "=r"((r)[19]), \
          "=r"((r)[20]), "=r"((r)[21]), "=r"((r)[22]), "=r"((r)[23]), \
          "=r"((r)[24]), "=r"((r)[25]), "=r"((r)[26]), "=r"((r)[27]), \
          "=r"((r)[28]), "=r"((r)[29]), "=r"((r)[30]), "=r"((r)[31]) \
        : "r"(addr))
#endif  // TCGEN_OK

// ---------------- kernel A: per-CTA histogram ----------------
__global__ __launch_bounds__(SCAN_TPB)
void count_kernel(const int* __restrict__ inds, int N) {
    const int cta = blockIdx.x, tid = threadIdx.x;
    const int base = cta * SCAN_TOKENS;
    int c[EXPERTS];
    #pragma unroll
    for (int q = 0; q < EXPERTS; ++q) c[q] = 0;
    for (int i = tid; i < SCAN_TOKENS; i += SCAN_TPB) {
        int g = base + i;
        if (g < N) {
            int e = inds[g];
            #pragma unroll
            for (int q = 0; q < EXPERTS; ++q) c[q] += (e == q);
        }
    }
    #pragma unroll
    for (int q = 0; q < EXPERTS; ++q)
        c[q] = __reduce_add_sync(0xffffffffu, c[q]);
    __shared__ int w[SCAN_TPB / 32][EXPERTS];
    if ((tid & 31) == 0) {
        #pragma unroll
        for (int q = 0; q < EXPERTS; ++q) w[tid >> 5][q] = c[q];
    }
    __syncthreads();
    if (tid < EXPERTS) {
        int s = 0;
        #pragma unroll
        for (int ww = 0; ww < SCAN_TPB / 32; ++ww) s += w[ww][tid];
        g_blockCnt[cta * EXPERTS + tid] = s;
    }
}

// ---------------- kernel B: scan (1 CTA) ----------------
__global__ __launch_bounds__(NUM_SCAN_CTAS)
void scan_kernel() {
    __shared__ int s[NUM_SCAN_CTAS];
    __shared__ int sTot[EXPERTS];
    const int tid = threadIdx.x;
    if (tid == 0) g_ticket = 0;
    for (int e = 0; e < EXPERTS; ++e) {
        int v = g_blockCnt[tid * EXPERTS + e];
        s[tid] = v;
        __syncthreads();
        for (int ofs = 1; ofs < NUM_SCAN_CTAS; ofs <<= 1) {
            int t = (tid >= ofs) ? s[tid - ofs] : 0;
            __syncthreads();
            s[tid] += t;
            __syncthreads();
        }
        if (tid == NUM_SCAN_CTAS - 1) sTot[e] = s[tid];
        g_blockBase[tid * EXPERTS + e] = s[tid] - v;
        __syncthreads();
    }
    if (tid == 0) {
        int off = 0, tofs = 0;
        for (int e = 0; e < EXPERTS; ++e) {
            g_cnt[e] = sTot[e];
            g_off[e] = off;
            g_tileOfs[e] = tofs;
            off  += sTot[e];
            tofs += (sTot[e] + TILE - 1) / TILE;
        }
        g_off[EXPERTS] = off;
        g_tileOfs[EXPERTS] = tofs;
    }
    __syncthreads();
    #pragma unroll
    for (int e = 0; e < EXPERTS; ++e)
        g_blockBase[tid * EXPERTS + e] += g_off[e];
}

// ---------------- kernel C: scatter token ids ----------------
__global__ __launch_bounds__(SCAN_TPB)
void scatter_kernel(const int* __restrict__ inds, int N) {
    __shared__ int ctr[EXPERTS];
    const int cta = blockIdx.x, tid = threadIdx.x;
    if (tid < EXPERTS) ctr[tid] = g_blockBase[cta * EXPERTS + tid];
    __syncthreads();
    const int base = cta * SCAN_TOKENS;
    for (int i = tid; i < SCAN_TOKENS; i += SCAN_TPB) {
        int g = base + i;
        if (g < N) {
            int e = inds[g];
            int slot = atomicAdd(&ctr[e], 1);
            g_perm[slot] = g;
        }
    }
}

// ---------------- kernel D: TS-mode tcgen05 bf16-split GEMM ----------------
extern __shared__ char dsm[];

__global__ __launch_bounds__(GBLOCK)
void gemm_kernel(const float* __restrict__ features,
                 const float* __restrict__ W,
                 const float* __restrict__ b,
                 float* __restrict__ out)
{
    char* base = (char*)(((uintptr_t)dsm + 1023) & ~(uintptr_t)1023);
    int*   sMeta = (int*)(base + OFF_META);
    int*   sTick = (int*)(base + OFF_TICK);

    const int tid = threadIdx.x;

    if (tid < 9)       sMeta[tid] = g_tileOfs[tid];
    else if (tid < 17) sMeta[tid] = g_off[tid - 9];
    else if (tid < 25) sMeta[tid] = g_cnt[tid - 17];

#if TCGEN_OK
    float* sB = (float*)(base + OFF_BIAS);
    const uint32_t sbase = smem_u32(base);
    const uint32_t mbar  = sbase + OFF_MBAR;
    const int wid   = tid >> 5;          // 0..7
    const int lane  = tid & 31;
    const int sub   = wid & 3;           // TMEM subpartition
    const int khalf = wid >> 2;          // 0: k 0..31, 1: k 32..63
    const int row   = sub * 32 + lane;   // token row 0..127
    const uint32_t woff = (uint32_t)sub << 21;   // TMEM lane-base bits

    if (tid == 0)
        asm volatile("mbarrier.init.shared.b64 [%0], 1;" :: "r"(mbar) : "memory");
    if (wid == 0)
        asm volatile("tcgen05.alloc.cta_group::1.sync.aligned.shared::cta.b32 [%0], %1;"
                     :: "r"(sbase + OFF_TMEM), "r"((uint32_t)TM_COLS) : "memory");
    __syncthreads();
    uint32_t tmem;
    asm volatile("ld.shared.b32 %0, [%1];" : "=r"(tmem) : "r"(sbase + OFF_TMEM));
    if (wid == 0)
        asm volatile("tcgen05.relinquish_alloc_permit.cta_group::1.sync.aligned;");

    const uint64_t dBH = make_desc(sbase + OFF_BH);
    const uint64_t dBL = make_desc(sbase + OFF_BL);

    const int totalTiles = sMeta[8];
    uint32_t ph = 0;
    int eCur = -1;

    for (;;) {
        if (tid == 0) *sTick = atomicAdd(&g_ticket, 1);
        __syncthreads();                 // also: prev LDTM done before acc reuse
        const int t = *sTick;
        if (t >= totalTiles) break;

        // tile info (uniform)
        int e = 0;
        #pragma unroll
        for (int q = 1; q < EXPERTS; ++q) if (t >= sMeta[q]) e = q;
        const int ti = t - sMeta[e];
        const int rowStart = sMeta[9 + e] + ti * TILE;
        const int Mt = min(TILE, sMeta[17 + e] - ti * TILE);

        // gather own half-row (128B = 8 LDG.128)
        const int tok = g_perm[rowStart + (row < Mt ? row : 0)];
        const float4* frow = (const float4*)(features + (size_t)tok * D + khalf * 32);
        float4 v[8];
        #pragma unroll
        for (int i = 0; i < 8; ++i) v[i] = frow[i];

        // expert weight staging (rare): threads 0..127 as before
        if (e != eCur) {
            if (tid < 128) {
                const int j  = tid >> 1;
                const int kh = (tid & 1) * 32;
                const float* wcol = W + (size_t)e * D * D + j;
                float wv[32];
                #pragma unroll
                for (int k = 0; k < 32; ++k) wv[k] = wcol[(size_t)(kh + k) * D];
                #pragma unroll
                for (int c = 0; c < 4; ++c) {
                    uint32_t hb[4], lb[4];
                    #pragma unroll
                    for (int p = 0; p < 4; ++p) {
                        float x0 = wv[c * 8 + 2 * p], x1 = wv[c * 8 + 2 * p + 1];
                        __nv_bfloat162 h = __floats2bfloat162_rn(x0, x1);
                        float2 hf = __bfloat1622float2(h);
                        __nv_bfloat162 l = __floats2bfloat162_rn(x0 - hf.x, x1 - hf.y);
                        hb[p] = bits2(h); lb[p] = bits2(l);
                    }
                    uint32_t off = (uint32_t)j * 128u + (uint32_t)(kh + c * 8) * 2u;
                    uint32_t sw  = off ^ ((off >> 3) & 0x70);
                    *(uint4*)(base + OFF_BH + sw) = make_uint4(hb[0], hb[1], hb[2], hb[3]);
                    *(uint4*)(base + OFF_BL + sw) = make_uint4(lb[0], lb[1], lb[2], lb[3]);
                }
                if (tid < D) sB[tid] = b[e * D + tid];
            }
            eCur = e;
        }

        // convert -> bf16 hi/lo and store A directly to TMEM (x16 per half)
        {
            uint32_t hi[16], lo[16];
            #pragma unroll
            for (int i = 0; i < 8; ++i) {
                float4 f = v[i];
                __nv_bfloat162 h0 = __floats2bfloat162_rn(f.x, f.y);
                __nv_bfloat162 h1 = __floats2bfloat162_rn(f.z, f.w);
                float2 p0 = __bfloat1622float2(h0), p1 = __bfloat1622float2(h1);
                __nv_bfloat162 l0 = __floats2bfloat162_rn(f.x - p0.x, f.y - p0.y);
                __nv_bfloat162 l1 = __floats2bfloat162_rn(f.z - p1.x, f.w - p1.y);
                hi[2 * i] = bits2(h0); hi[2 * i + 1] = bits2(h1);
                lo[2 * i] = bits2(l0); lo[2 * i + 1] = bits2(l1);
            }
            TTM_ST_X16(tmem + TM_AHI + khalf * 16 + woff, hi);
            TTM_ST_X16(tmem + TM_ALO + khalf * 16 + woff, lo);
            asm volatile("tcgen05.wait::st.sync.aligned;" ::: "memory");
        }
        asm volatile("fence.proxy.async.shared::cta;" ::: "memory");
        asm volatile("tcgen05.fence::before_thread_sync;" ::: "memory");
        __syncthreads();                 // A in TMEM + B in smem visible

        // MMA: acc = Ah@Bh + Ah@Bl + Al@Bh   (12 chunk-MMAs, K=16 each)
        if (wid == 0 && elect_one_pred()) {
            asm volatile("tcgen05.fence::after_thread_sync;" ::: "memory");
            const uint32_t acc = tmem + TM_ACC;
            #pragma unroll
            for (int k = 0; k < 4; ++k)
                mma_f16_ts(acc, tmem + TM_AHI + k * 8, dBH + 2 * k, IDESC_BF16, k > 0);
            #pragma unroll
            for (int k = 0; k < 4; ++k)
                mma_f16_ts(acc, tmem + TM_AHI + k * 8, dBL + 2 * k, IDESC_BF16, 1);
            #pragma unroll
            for (int k = 0; k < 4; ++k)
                mma_f16_ts(acc, tmem + TM_ALO + k * 8, dBH + 2 * k, IDESC_BF16, 1);
            asm volatile(
                "tcgen05.commit.cta_group::1.mbarrier::arrive::one.shared::cluster.b64 [%0];"
                :: "r"(mbar) : "memory");
        }

        mbar_wait(mbar, ph);
        ph ^= 1;
        asm volatile("tcgen05.fence::after_thread_sync;" ::: "memory");

        // epilogue: each warp reads its 32 acc cols, bias-add, store half-row
        uint32_t dr[32];
        LDTM_X32(dr, tmem + TM_ACC + khalf * 32 + woff);
        asm volatile("tcgen05.wait::ld.sync.aligned;" ::: "memory");

        if (row < Mt) {
            float4* orow = (float4*)(out + (size_t)tok * D + khalf * 32);
            #pragma unroll
            for (int q = 0; q < 8; ++q) {
                float4 bb = *(const float4*)(sB + khalf * 32 + q * 4);
                float4 o;
                o.x = __uint_as_float(dr[q * 4 + 0]) + bb.x;
                o.y = __uint_as_float(dr[q * 4 + 1]) + bb.y;
                o.z = __uint_as_float(dr[q * 4 + 2]) + bb.z;
                o.w = __uint_as_float(dr[q * 4 + 3]) + bb.w;
                orow[q] = o;
            }
        }
        asm volatile("tcgen05.fence::before_thread_sync;" ::: "memory");
    }

    __syncthreads();
    if (tid == 0)
        asm volatile("mbarrier.inval.shared.b64 [%0];" :: "r"(mbar) : "memory");
    __syncthreads();
    if (wid == 0)
        asm volatile("tcgen05.dealloc.cta_group::1.sync.aligned.b32 %0, %1;"
                     :: "r"(tmem), "r"((uint32_t)TM_COLS));

#else   // !TCGEN_OK — generic-PTX fallback (compiles everywhere; sm_103a cubin runs)
    __syncthreads();
    const int totalTiles = sMeta[8];
    const int row   = ((tid >> 5) & 3) * 32 + (tid & 31);
    const int khalf = tid >> 7;
    for (;;) {
        if (tid == 0) *sTick = atomicAdd(&g_ticket, 1);
        __syncthreads();
        const int t = *sTick;
        if (t >= totalTiles) break;

        int e = 0;
        #pragma unroll
        for (int q = 1; q < EXPERTS; ++q) if (t >= sMeta[q]) e = q;
        const int ti = t - sMeta[e];
        const int rowStart = sMeta[9 + e] + ti * TILE;
        const int Mt = min(TILE, sMeta[17 + e] - ti * TILE);

        const int tok = g_perm[rowStart + (row < Mt ? row : 0)];
        const float* frow = features + (size_t)tok * D;
        float v[D];
        #pragma unroll
        for (int k = 0; k < D; ++k) v[k] = frow[k];

        if (row < Mt) {
            const float* We = W + (size_t)e * D * D;
            for (int j = khalf * 32; j < khalf * 32 + 32; ++j) {
                float s = b[e * D + j];
                #pragma unroll 16
                for (int k = 0; k < D; ++k) s = fmaf(v[k], We[(size_t)k * D + j], s);
                out[(size_t)tok * D + j] = s;
            }
        }
        __syncthreads();
    }
#endif
}

// ---------------- launch ----------------
extern "C" void kernel_launch(void* const* d_in, const int* in_sizes, int n_in,
                              void* d_out, int out_size) {
    const float* features = (const float*)d_in[0];
    const int*   inds     = (const int*)d_in[1];
    const float* W        = (const float*)d_in[2];
    const float* b        = (const float*)d_in[3];
    float*       out      = (float*)d_out;

    int N = in_sizes[0] / D;

    (void)cudaFuncSetAttribute(gemm_kernel,
                               cudaFuncAttributeMaxDynamicSharedMemorySize,
                               SMEM_SZ);

    int nScan = (N + SCAN_TOKENS - 1) / SCAN_TOKENS;
    count_kernel<<<nScan, SCAN_TPB>>>(inds, N);
    scan_kernel<<<1, NUM_SCAN_CTAS>>>();
    scatter_kernel<<<nScan, SCAN_TPB>>>(inds, N);
    gemm_kernel<<<NCTA_GEMM, GBLOCK, SMEM_SZ>>>(features, W, b, out);
}

// round 14
// speedup vs baseline: 1.3696x; 1.3696x over previous
#include <cuda_runtime.h>
#include <cuda_bf16.h>
#include <cstdint>

#define D        64
#define EXPERTS  8
#define NTOK     (1 << 20)
#define SCAN_TPB 256
#define SCAN_TOKENS 4096
#define NUM_SCAN_CTAS (NTOK / SCAN_TOKENS)   // 256
#define TILE     128
#define GBLOCK   256
#define NCTA_GEMM 592

#if defined(__CUDA_ARCH_FEAT_SM103_ALL) || \
    (defined(__CUDA_ARCH_SPECIFIC__) && (__CUDA_ARCH_SPECIFIC__ == 1030))
#define TCGEN_OK 1
#else
#define TCGEN_OK 0
#endif

// idesc kind::f16: dtype F32(1<<4) | atype BF16(1<<7) | btype BF16(1<<10)
//                  | (N/8)<<17 | (M/16)<<24   => M=128,N=64
#define IDESC_BF16 0x8100490u

// smem offsets (base is 1KB-aligned)
#define OFF_BH   0        // B hi: 64 rows x 128B SW128
#define OFF_BL   8192     // B lo
#define OFF_STG  16384    // per-warp staging: 8 x 4KB (32 half-rows x 128B)
#define OFF_BIAS 49152    // 64 floats
#define OFF_MBAR 49408    // 8B
#define OFF_TMEM 49416    // 4B
#define OFF_META 49424    // 25 ints
#define OFF_TICK 49524    // 1 int
#define SMEM_SZ  (49536 + 1024)

// TMEM columns: A hi [0,32), A lo [32,64), acc [64,128)
#define TM_AHI  0
#define TM_ALO  32
#define TM_ACC  64
#define TM_COLS 128

// ---------------- device scratch ----------------
__device__ int g_perm[NTOK];
__device__ int g_blockCnt[NUM_SCAN_CTAS * EXPERTS];
__device__ int g_blockBase[NUM_SCAN_CTAS * EXPERTS];
__device__ int g_cnt[EXPERTS];
__device__ int g_off[EXPERTS + 1];
__device__ int g_tileOfs[EXPERTS + 1];
__device__ int g_ticket;

// ---------------- helpers ----------------
__device__ __forceinline__ uint32_t smem_u32(const void* p) {
    uint32_t a;
    asm("{ .reg .u64 t; cvta.to.shared.u64 t, %1; cvt.u32.u64 %0, t; }"
        : "=r"(a) : "l"(p));
    return a;
}
__device__ __forceinline__ uint32_t bits2(__nv_bfloat162 h) {
    return *reinterpret_cast<uint32_t*>(&h);
}

#if TCGEN_OK
__device__ __forceinline__ uint32_t elect_one_pred() {
    uint32_t p;
    asm volatile("{\n\t.reg .pred p;\n\telect.sync _|p, 0xFFFFFFFF;\n\t"
                 "selp.b32 %0, 1, 0, p;\n\t}" : "=r"(p));
    return p;
}
__device__ __forceinline__ uint64_t make_desc(uint32_t addr) {
    // SW128 (layout 2), Blackwell version=1, SBO=64, LBO=1
    const uint64_t base = (2ull << 61) | (1ull << 46) | (64ull << 32) | (1ull << 16);
    return base | ((uint64_t)(addr >> 4) & 0x3FFF);
}
// TS form: A in TMEM
__device__ __forceinline__ void mma_f16_ts(uint32_t d_tmem, uint32_t a_tmem,
                                           uint64_t b_desc, uint32_t idesc,
                                           uint32_t accum) {
    asm volatile(
        "{\n\t.reg .pred p;\n\tsetp.ne.u32 p, %5, 0;\n\t"
        "tcgen05.mma.cta_group::1.kind::f16 [%0], [%1], %2, %3, {%4, %4, %4, %4}, p;\n\t}"
        :: "r"(d_tmem), "r"(a_tmem), "l"(b_desc), "r"(idesc), "r"(0u), "r"(accum)
        : "memory");
}
__device__ __forceinline__ void mbar_wait(uint32_t mbar, uint32_t parity) {
    asm volatile(
        "{\n\t.reg .pred P;\n\t"
        "WL_%=:\n\t"
        "mbarrier.try_wait.parity.acquire.cta.shared::cta.b64 P, [%0], %1, 0x989680;\n\t"
        "@P bra.uni WD_%=;\n\t"
        "bra.uni WL_%=;\n\t"
        "WD_%=:\n\t}"
        :: "r"(mbar), "r"(parity) : "memory");
}
#define TTM_ST_X16(addr, r) \
    asm volatile( \
        "tcgen05.st.sync.aligned.32x32b.x16.b32 [%0], " \
        "{%1, %2, %3, %4, %5, %6, %7, %8, " \
        " %9, %10, %11, %12, %13, %14, %15, %16};" \
        :: "r"(addr), \
           "r"((r)[0]),  "r"((r)[1]),  "r"((r)[2]),  "r"((r)[3]), \
           "r"((r)[4]),  "r"((r)[5]),  "r"((r)[6]),  "r"((r)[7]), \
           "r"((r)[8]),  "r"((r)[9]),  "r"((r)[10]), "r"((r)[11]), \
           "r"((r)[12]), "r"((r)[13]), "r"((r)[14]), "r"((r)[15]) \
        : "memory")
#define LDTM_X32(r, addr) \
    asm volatile( \
        "tcgen05.ld.sync.aligned.32x32b.x32.b32 " \
        "{%0, %1, %2, %3, %4, %5, %6, %7, " \
        " %8, %9, %10, %11, %12, %13, %14, %15, " \
        " %16, %17, %18, %19, %20, %21, %22, %23, " \
        " %24, %25, %26, %27, %28, %29, %30, %31}, [%32];" \
        : "=r"((r)[0]),  "=r"((r)[1]),  "=r"((r)[2]),  "=r"((r)[3]), \
          "=r"((r)[4]),  "=r"((r)[5]),  "=r"((r)[6]),  "=r"((r)[7]), \
          "=r"((r)[8]),  "=r"((r)[9]),  "=r"((r)[10]), "=r"((r)[11]), \
          "=r"((r)[12]), "=r"((r)[13]), "=r"((r)[14]), "=r"((r)[15]), \
          "=r"((r)[16]), "=r"((r)[17]), "=r"((r)[18]), "=r"((r)[19]), \
          "=r"((r)[20]), "=r"((r)[21]), "=r"((r)[22]), "=r"((r)[23]), \
          "=r"((r)[24]), "=r"((r)[25]), "=r"((r)[26]), "=r"((r)[27]), \
          "=r"((r)[28]), "=r"((r)[29]), "=r"((r)[30]), "=r"((r)[31]) \
        : "r"(addr))
#endif  // TCGEN_OK

// ---------------- kernel A: per-CTA histogram ----------------
__global__ __launch_bounds__(SCAN_TPB)
void count_kernel(const int* __restrict__ inds, int N) {
    const int cta = blockIdx.x, tid = threadIdx.x;
    const int base = cta * SCAN_TOKENS;
    int c[EXPERTS];
    #pragma unroll
    for (int q = 0; q < EXPERTS; ++q) c[q] = 0;
    for (int i = tid; i < SCAN_TOKENS; i += SCAN_TPB) {
        int g = base + i;
        if (g < N) {
            int e = inds[g];
            #pragma unroll
            for (int q = 0; q < EXPERTS; ++q) c[q] += (e == q);
        }
    }
    #pragma unroll
    for (int q = 0; q < EXPERTS; ++q)
        c[q] = __reduce_add_sync(0xffffffffu, c[q]);
    __shared__ int w[SCAN_TPB / 32][EXPERTS];
    if ((tid & 31) == 0) {
        #pragma unroll
        for (int q = 0; q < EXPERTS; ++q) w[tid >> 5][q] = c[q];
    }
    __syncthreads();
    if (tid < EXPERTS) {
        int s = 0;
        #pragma unroll
        for (int ww = 0; ww < SCAN_TPB / 32; ++ww) s += w[ww][tid];
        g_blockCnt[cta * EXPERTS + tid] = s;
    }
}

// ---------------- kernel B: scan (1 CTA) ----------------
__global__ __launch_bounds__(NUM_SCAN_CTAS)
void scan_kernel() {
    __shared__ int s[NUM_SCAN_CTAS];
    __shared__ int sTot[EXPERTS];
    const int tid = threadIdx.x;
    if (tid == 0) g_ticket = 0;
    for (int e = 0; e < EXPERTS; ++e) {
        int v = g_blockCnt[tid * EXPERTS + e];
        s[tid] = v;
        __syncthreads();
        for (int ofs = 1; ofs < NUM_SCAN_CTAS; ofs <<= 1) {
            int t = (tid >= ofs) ? s[tid - ofs] : 0;
            __syncthreads();
            s[tid] += t;
            __syncthreads();
        }
        if (tid == NUM_SCAN_CTAS - 1) sTot[e] = s[tid];
        g_blockBase[tid * EXPERTS + e] = s[tid] - v;
        __syncthreads();
    }
    if (tid == 0) {
        int off = 0, tofs = 0;
        for (int e = 0; e < EXPERTS; ++e) {
            g_cnt[e] = sTot[e];
            g_off[e] = off;
            g_tileOfs[e] = tofs;
            off  += sTot[e];
            tofs += (sTot[e] + TILE - 1) / TILE;
        }
        g_off[EXPERTS] = off;
        g_tileOfs[EXPERTS] = tofs;
    }
    __syncthreads();
    #pragma unroll
    for (int e = 0; e < EXPERTS; ++e)
        g_blockBase[tid * EXPERTS + e] += g_off[e];
}

// ---------------- kernel C: scatter token ids ----------------
__global__ __launch_bounds__(SCAN_TPB)
void scatter_kernel(const int* __restrict__ inds, int N) {
    __shared__ int ctr[EXPERTS];
    const int cta = blockIdx.x, tid = threadIdx.x;
    if (tid < EXPERTS) ctr[tid] = g_blockBase[cta * EXPERTS + tid];
    __syncthreads();
    const int base = cta * SCAN_TOKENS;
    for (int i = tid; i < SCAN_TOKENS; i += SCAN_TPB) {
        int g = base + i;
        if (g < N) {
            int e = inds[g];
            int slot = atomicAdd(&ctr[e], 1);
            g_perm[slot] = g;
        }
    }
}

// ---------------- kernel D: TS-mode tcgen05 GEMM, coalesced gather/scatter ----------------
extern __shared__ char dsm[];

__global__ __launch_bounds__(GBLOCK)
void gemm_kernel(const float* __restrict__ features,
                 const float* __restrict__ W,
                 const float* __restrict__ b,
                 float* __restrict__ out)
{
    char* base = (char*)(((uintptr_t)dsm + 1023) & ~(uintptr_t)1023);
    int*   sMeta = (int*)(base + OFF_META);
    int*   sTick = (int*)(base + OFF_TICK);

    const int tid = threadIdx.x;

    if (tid < 9)       sMeta[tid] = g_tileOfs[tid];
    else if (tid < 17) sMeta[tid] = g_off[tid - 9];
    else if (tid < 25) sMeta[tid] = g_cnt[tid - 17];

#if TCGEN_OK
    float* sB = (float*)(base + OFF_BIAS);
    const uint32_t sbase = smem_u32(base);
    const uint32_t mbar  = sbase + OFF_MBAR;
    const int wid   = tid >> 5;          // 0..7
    const int lane  = tid & 31;
    const int sub   = wid & 3;           // TMEM subpartition
    const int khalf = wid >> 2;          // 0: k 0..31, 1: k 32..63
    const int row   = sub * 32 + lane;   // tile row 0..127
    const uint32_t woff = (uint32_t)sub << 21;   // TMEM lane-base bits
    char* stg = base + OFF_STG + wid * 4096;     // per-warp staging (32 x 128B)
    const int c8 = lane & 7;             // chunk within half-row
    const int g4 = lane >> 3;            // row-subgroup within gather instr

    if (tid == 0)
        asm volatile("mbarrier.init.shared.b64 [%0], 1;" :: "r"(mbar) : "memory");
    if (wid == 0)
        asm volatile("tcgen05.alloc.cta_group::1.sync.aligned.shared::cta.b32 [%0], %1;"
                     :: "r"(sbase + OFF_TMEM), "r"((uint32_t)TM_COLS) : "memory");
    __syncthreads();
    uint32_t tmem;
    asm volatile("ld.shared.b32 %0, [%1];" : "=r"(tmem) : "r"(sbase + OFF_TMEM));
    if (wid == 0)
        asm volatile("tcgen05.relinquish_alloc_permit.cta_group::1.sync.aligned;");

    const uint64_t dBH = make_desc(sbase + OFF_BH);
    const uint64_t dBL = make_desc(sbase + OFF_BL);

    const int totalTiles = sMeta[8];
    uint32_t ph = 0;
    int eCur = -1;

    for (;;) {
        if (tid == 0) *sTick = atomicAdd(&g_ticket, 1);
        __syncthreads();
        const int t = *sTick;
        if (t >= totalTiles) break;

        // tile info (uniform)
        int e = 0;
        #pragma unroll
        for (int q = 1; q < EXPERTS; ++q) if (t >= sMeta[q]) e = q;
        const int ti = t - sMeta[e];
        const int rowStart = sMeta[9 + e] + ti * TILE;
        const int Mt = min(TILE, sMeta[17 + e] - ti * TILE);

        // perm entry for own row (coalesced 128B per warp)
        const int tokr = g_perm[rowStart + (row < Mt ? row : 0)];

        // ---- coalesced gather: 8 lanes per half-row -> swizzled staging ----
        #pragma unroll
        for (int i = 0; i < 8; ++i) {
            const int lr  = 4 * i + g4;                         // local row 0..31
            const int tko = __shfl_sync(0xffffffffu, tokr, lr);
            const float4* src =
                (const float4*)(features + (size_t)tko * D + khalf * 32 + c8 * 4);
            *(uint4*)(stg + lr * 128 + (((lr & 7) ^ c8) << 4)) = *(const uint4*)src;
        }
        __syncwarp();

        // ---- load own half-row from staging (4-phase, conflict-floor) ----
        float4 v[8];
        #pragma unroll
        for (int c = 0; c < 8; ++c)
            v[c] = *(const float4*)(stg + lane * 128 + (((lane & 7) ^ c) << 4));

        // expert weight staging (rare)
        if (e != eCur) {
            if (tid < 128) {
                const int j  = tid >> 1;
                const int kh = (tid & 1) * 32;
                const float* wcol = W + (size_t)e * D * D + j;
                float wv[32];
                #pragma unroll
                for (int k = 0; k < 32; ++k) wv[k] = wcol[(size_t)(kh + k) * D];
                #pragma unroll
                for (int c = 0; c < 4; ++c) {
                    uint32_t hb[4], lb[4];
                    #pragma unroll
                    for (int p = 0; p < 4; ++p) {
                        float x0 = wv[c * 8 + 2 * p], x1 = wv[c * 8 + 2 * p + 1];
                        __nv_bfloat162 h = __floats2bfloat162_rn(x0, x1);
                        float2 hf = __bfloat1622float2(h);
                        __nv_bfloat162 l = __floats2bfloat162_rn(x0 - hf.x, x1 - hf.y);
                        hb[p] = bits2(h); lb[p] = bits2(l);
                    }
                    uint32_t off = (uint32_t)j * 128u + (uint32_t)(kh + c * 8) * 2u;
                    uint32_t sw  = off ^ ((off >> 3) & 0x70);
                    *(uint4*)(base + OFF_BH + sw) = make_uint4(hb[0], hb[1], hb[2], hb[3]);
                    *(uint4*)(base + OFF_BL + sw) = make_uint4(lb[0], lb[1], lb[2], lb[3]);
                }
                if (tid < D) sB[tid] = b[e * D + tid];
            }
            eCur = e;
        }

        // ---- convert -> bf16 hi/lo, store A to TMEM ----
        {
            uint32_t hi[16], lo[16];
            #pragma unroll
            for (int i = 0; i < 8; ++i) {
                float4 f = v[i];
                __nv_bfloat162 h0 = __floats2bfloat162_rn(f.x, f.y);
                __nv_bfloat162 h1 = __floats2bfloat162_rn(f.z, f.w);
                float2 p0 = __bfloat1622float2(h0), p1 = __bfloat1622float2(h1);
                __nv_bfloat162 l0 = __floats2bfloat162_rn(f.x - p0.x, f.y - p0.y);
                __nv_bfloat162 l1 = __floats2bfloat162_rn(f.z - p1.x, f.w - p1.y);
                hi[2 * i] = bits2(h0); hi[2 * i + 1] = bits2(h1);
                lo[2 * i] = bits2(l0); lo[2 * i + 1] = bits2(l1);
            }
            TTM_ST_X16(tmem + TM_AHI + khalf * 16 + woff, hi);
            TTM_ST_X16(tmem + TM_ALO + khalf * 16 + woff, lo);
            asm volatile("tcgen05.wait::st.sync.aligned;" ::: "memory");
        }
        asm volatile("fence.proxy.async.shared::cta;" ::: "memory");
        asm volatile("tcgen05.fence::before_thread_sync;" ::: "memory");
        __syncthreads();                 // A in TMEM + B in smem visible

        // ---- MMA: acc = Ah@Bh + Ah@Bl + Al@Bh ----
        if (wid == 0 && elect_one_pred()) {
            asm volatile("tcgen05.fence::after_thread_sync;" ::: "memory");
            const uint32_t acc = tmem + TM_ACC;
            #pragma unroll
            for (int k = 0; k < 4; ++k)
                mma_f16_ts(acc, tmem + TM_AHI + k * 8, dBH + 2 * k, IDESC_BF16, k > 0);
            #pragma unroll
            for (int k = 0; k < 4; ++k)
                mma_f16_ts(acc, tmem + TM_AHI + k * 8, dBL + 2 * k, IDESC_BF16, 1);
            #pragma unroll
            for (int k = 0; k < 4; ++k)
                mma_f16_ts(acc, tmem + TM_ALO + k * 8, dBH + 2 * k, IDESC_BF16, 1);
            asm volatile(
                "tcgen05.commit.cta_group::1.mbarrier::arrive::one.shared::cluster.b64 [%0];"
                :: "r"(mbar) : "memory");
        }

        mbar_wait(mbar, ph);
        ph ^= 1;
        asm volatile("tcgen05.fence::after_thread_sync;" ::: "memory");

        // ---- epilogue: LDTM (lane=row) -> bias -> staging -> coalesced STG ----
        uint32_t dr[32];
        LDTM_X32(dr, tmem + TM_ACC + khalf * 32 + woff);
        asm volatile("tcgen05.wait::ld.sync.aligned;" ::: "memory");

        #pragma unroll
        for (int q = 0; q < 8; ++q) {
            float4 bb = *(const float4*)(sB + khalf * 32 + q * 4);
            float4 o;
            o.x = __uint_as_float(dr[q * 4 + 0]) + bb.x;
            o.y = __uint_as_float(dr[q * 4 + 1]) + bb.y;
            o.z = __uint_as_float(dr[q * 4 + 2]) + bb.z;
            o.w = __uint_as_float(dr[q * 4 + 3]) + bb.w;
            *(uint4*)(stg + lane * 128 + (((lane & 7) ^ q) << 4)) = *(uint4*)&o;
        }
        __syncwarp();
        #pragma unroll
        for (int i = 0; i < 8; ++i) {
            const int lr  = 4 * i + g4;
            const int tko = __shfl_sync(0xffffffffu, tokr, lr);
            if (sub * 32 + lr < Mt) {
                uint4 val = *(const uint4*)(stg + lr * 128 + (((lr & 7) ^ c8) << 4));
                *(uint4*)(out + (size_t)tko * D + khalf * 32 + c8 * 4) = val;
            }
        }
        asm volatile("tcgen05.fence::before_thread_sync;" ::: "memory");
    }

    __syncthreads();
    if (tid == 0)
        asm volatile("mbarrier.inval.shared.b64 [%0];" :: "r"(mbar) : "memory");
    __syncthreads();
    if (wid == 0)
        asm volatile("tcgen05.dealloc.cta_group::1.sync.aligned.b32 %0, %1;"
                     :: "r"(tmem), "r"((uint32_t)TM_COLS));

#else   // !TCGEN_OK — generic-PTX fallback (compiles everywhere; sm_103a cubin runs)
    __syncthreads();
    const int totalTiles = sMeta[8];
    const int row   = ((tid >> 5) & 3) * 32 + (tid & 31);
    const int khalf = tid >> 7;
    for (;;) {
        if (tid == 0) *sTick = atomicAdd(&g_ticket, 1);
        __syncthreads();
        const int t = *sTick;
        if (t >= totalTiles) break;

        int e = 0;
        #pragma unroll
        for (int q = 1; q < EXPERTS; ++q) if (t >= sMeta[q]) e = q;
        const int ti = t - sMeta[e];
        const int rowStart = sMeta[9 + e] + ti * TILE;
        const int Mt = min(TILE, sMeta[17 + e] - ti * TILE);

        const int tok = g_perm[rowStart + (row < Mt ? row : 0)];
        const float* frow = features + (size_t)tok * D;
        float v[D];
        #pragma unroll
        for (int k = 0; k < D; ++k) v[k] = frow[k];

        if (row < Mt) {
            const float* We = W + (size_t)e * D * D;
            for (int j = khalf * 32; j < khalf * 32 + 32; ++j) {
                float s = b[e * D + j];
                #pragma unroll 16
                for (int k = 0; k < D; ++k) s = fmaf(v[k], We[(size_t)k * D + j], s);
                out[(size_t)tok * D + j] = s;
            }
        }
        __syncthreads();
    }
#endif
}

// ---------------- launch ----------------
extern "C" void kernel_launch(void* const* d_in, const int* in_sizes, int n_in,
                              void* d_out, int out_size) {
    const float* features = (const float*)d_in[0];
    const int*   inds     = (const int*)d_in[1];
    const float* W        = (const float*)d_in[2];
    const float* b        = (const float*)d_in[3];
    float*       out      = (float*)d_out;

    int N = in_sizes[0] / D;

    (void)cudaFuncSetAttribute(gemm_kernel,
                               cudaFuncAttributeMaxDynamicSharedMemorySize,
                               SMEM_SZ);

    int nScan = (N + SCAN_TOKENS - 1) / SCAN_TOKENS;
    count_kernel<<<nScan, SCAN_TPB>>>(inds, N);
    scan_kernel<<<1, NUM_SCAN_CTAS>>>();
    scatter_kernel<<<nScan, SCAN_TPB>>>(inds, N);
    gemm_kernel<<<NCTA_GEMM, GBLOCK, SMEM_SZ>>>(features, W, b, out);
}

// round 15
// speedup vs baseline: 1.4010x; 1.0230x over previous
#include <cuda_runtime.h>
#include <cuda_bf16.h>
#include <cstdint>

#define D        64
#define EXPERTS  8
#define NTOK     (1 << 20)
#define SCAN_TPB 256
#define SCAN_TOKENS 4096
#define NUM_SCAN_CTAS (NTOK / SCAN_TOKENS)   // 256
#define TILE     128
#define GBLOCK   256
#define NCTA_GEMM 296

#if defined(__CUDA_ARCH_FEAT_SM103_ALL) || \
    (defined(__CUDA_ARCH_SPECIFIC__) && (__CUDA_ARCH_SPECIFIC__ == 1030))
#define TCGEN_OK 1
#else
#define TCGEN_OK 0
#endif

// idesc kind::f16: dtype F32(1<<4) | atype BF16(1<<7) | btype BF16(1<<10)
//                  | (N/8)<<17 | (M/16)<<24   => M=128,N=64
#define IDESC_BF16 0x8100490u

// smem offsets (base is 1KB-aligned)
#define OFF_BH   0        // B hi: 64 rows x 128B SW128
#define OFF_BL   8192     // B lo
#define OFF_STG  16384    // staging: 2 bufs x 8 warps x 4KB = 64KB
#define OFF_BIAS 81920    // 64 floats
#define OFF_MBAR 82176    // 8B
#define OFF_TMEM 82184    // 4B
#define OFF_META 82192    // 25 ints
#define OFF_TICK 82292    // 1 int
#define SMEM_SZ  (82304 + 1024)

// TMEM columns: A hi [0,32), A lo [32,64), acc [64,128)
#define TM_AHI  0
#define TM_ALO  32
#define TM_ACC  64
#define TM_COLS 128

// ---------------- device scratch ----------------
__device__ int g_perm[NTOK];
__device__ int g_blockCnt[NUM_SCAN_CTAS * EXPERTS];
__device__ int g_blockBase[NUM_SCAN_CTAS * EXPERTS];
__device__ int g_cnt[EXPERTS];
__device__ int g_off[EXPERTS + 1];
__device__ int g_tileOfs[EXPERTS + 1];
__device__ int g_ticket;

// ---------------- helpers ----------------
__device__ __forceinline__ uint32_t smem_u32(const void* p) {
    uint32_t a;
    asm("{ .reg .u64 t; cvta.to.shared.u64 t, %1; cvt.u32.u64 %0, t; }"
        : "=r"(a) : "l"(p));
    return a;
}
__device__ __forceinline__ uint32_t bits2(__nv_bfloat162 h) {
    return *reinterpret_cast<uint32_t*>(&h);
}

#if TCGEN_OK
__device__ __forceinline__ uint32_t elect_one_pred() {
    uint32_t p;
    asm volatile("{\n\t.reg .pred p;\n\telect.sync _|p, 0xFFFFFFFF;\n\t"
                 "selp.b32 %0, 1, 0, p;\n\t}" : "=r"(p));
    return p;
}
__device__ __forceinline__ uint64_t make_desc(uint32_t addr) {
    // SW128 (layout 2), Blackwell version=1, SBO=64, LBO=1
    const uint64_t base = (2ull << 61) | (1ull << 46) | (64ull << 32) | (1ull << 16);
    return base | ((uint64_t)(addr >> 4) & 0x3FFF);
}
// TS form: A in TMEM
__device__ __forceinline__ void mma_f16_ts(uint32_t d_tmem, uint32_t a_tmem,
                                           uint64_t b_desc, uint32_t idesc,
                                           uint32_t accum) {
    asm volatile(
        "{\n\t.reg .pred p;\n\tsetp.ne.u32 p, %5, 0;\n\t"
        "tcgen05.mma.cta_group::1.kind::f16 [%0], [%1], %2, %3, {%4, %4, %4, %4}, p;\n\t}"
        :: "r"(d_tmem), "r"(a_tmem), "l"(b_desc), "r"(idesc), "r"(0u), "r"(accum)
        : "memory");
}
__device__ __forceinline__ void mbar_wait(uint32_t mbar, uint32_t parity) {
    asm volatile(
        "{\n\t.reg .pred P;\n\t"
        "WL_%=:\n\t"
        "mbarrier.try_wait.parity.acquire.cta.shared::cta.b64 P, [%0], %1, 0x989680;\n\t"
        "@P bra.uni WD_%=;\n\t"
        "bra.uni WL_%=;\n\t"
        "WD_%=:\n\t}"
        :: "r"(mbar), "r"(parity) : "memory");
}
#define TTM_ST_X16(addr, r) \
    asm volatile( \
        "tcgen05.st.sync.aligned.32x32b.x16.b32 [%0], " \
        "{%1, %2, %3, %4, %5, %6, %7, %8, " \
        " %9, %10, %11, %12, %13, %14, %15, %16};" \
        :: "r"(addr), \
           "r"((r)[0]),  "r"((r)[1]),  "r"((r)[2]),  "r"((r)[3]), \
           "r"((r)[4]),  "r"((r)[5]),  "r"((r)[6]),  "r"((r)[7]), \
           "r"((r)[8]),  "r"((r)[9]),  "r"((r)[10]), "r"((r)[11]), \
           "r"((r)[12]), "r"((r)[13]), "r"((r)[14]), "r"((r)[15]) \
        : "memory")
#define LDTM_X32(r, addr) \
    asm volatile( \
        "tcgen05.ld.sync.aligned.32x32b.x32.b32 " \
        "{%0, %1, %2, %3, %4, %5, %6, %7, " \
        " %8, %9, %10, %11, %12, %13, %14, %15, " \
        " %16, %17, %18, %19, %20, %21, %22, %23, " \
        " %24, %25, %26, %27, %28, %29, %30, %31}, [%32];" \
        : "=r"((r)[0]),  "=r"((r)[1]),  "=r"((r)[2]),  "=r"((r)[3]), \
          "=r"((r)[4]),  "=r"((r)[5]),  "=r"((r)[6]),  "=r"((r)[7]), \
          "=r"((r)[8]),  "=r"((r)[9]),  "=r"((r)[10]), "=r"((r)[11]), \
          "=r"((r)[12]), "=r"((r)[13]), "=r"((r)[14]), "=r"((r)[15]), \
          "=r"((r)[16]), "=r"((r)[17]), "=r"((r)[18]), "=r"((r)[19]), \
          "=r"((r)[20]), "=r"((r)[21]), "=r"((r)[22]), "=r"((r)[23]), \
          "=r"((r)[24]), "=r"((r)[25]), "=r"((r)[26]), "=r"((r)[27]), \
          "=r"((r)[28]), "=r"((r)[29]), "=r"((r)[30]), "=r"((r)[31]) \
        : "r"(addr))
#endif  // TCGEN_OK

// ---------------- kernel A: per-CTA histogram ----------------
__global__ __launch_bounds__(SCAN_TPB)
void count_kernel(const int* __restrict__ inds, int N) {
    const int cta = blockIdx.x, tid = threadIdx.x;
    const int base = cta * SCAN_TOKENS;
    int c[EXPERTS];
    #pragma unroll
    for (int q = 0; q < EXPERTS; ++q) c[q] = 0;
    for (int i = tid; i < SCAN_TOKENS; i += SCAN_TPB) {
        int g = base + i;
        if (g < N) {
            int e = inds[g];
            #pragma unroll
            for (int q = 0; q < EXPERTS; ++q) c[q] += (e == q);
        }
    }
    #pragma unroll
    for (int q = 0; q < EXPERTS; ++q)
        c[q] = __reduce_add_sync(0xffffffffu, c[q]);
    __shared__ int w[SCAN_TPB / 32][EXPERTS];
    if ((tid & 31) == 0) {
        #pragma unroll
        for (int q = 0; q < EXPERTS; ++q) w[tid >> 5][q] = c[q];
    }
    __syncthreads();
    if (tid < EXPERTS) {
        int s = 0;
        #pragma unroll
        for (int ww = 0; ww < SCAN_TPB / 32; ++ww) s += w[ww][tid];
        g_blockCnt[cta * EXPERTS + tid] = s;
    }
}

// ---------------- kernel B: scan (1 CTA) ----------------
__global__ __launch_bounds__(NUM_SCAN_CTAS)
void scan_kernel() {
    __shared__ int s[NUM_SCAN_CTAS];
    __shared__ int sTot[EXPERTS];
    const int tid = threadIdx.x;
    if (tid == 0) g_ticket = 0;
    for (int e = 0; e < EXPERTS; ++e) {
        int v = g_blockCnt[tid * EXPERTS + e];
        s[tid] = v;
        __syncthreads();
        for (int ofs = 1; ofs < NUM_SCAN_CTAS; ofs <<= 1) {
            int t = (tid >= ofs) ? s[tid - ofs] : 0;
            __syncthreads();
            s[tid] += t;
            __syncthreads();
        }
        if (tid == NUM_SCAN_CTAS - 1) sTot[e] = s[tid];
        g_blockBase[tid * EXPERTS + e] = s[tid] - v;
        __syncthreads();
    }
    if (tid == 0) {
        int off = 0, tofs = 0;
        for (int e = 0; e < EXPERTS; ++e) {
            g_cnt[e] = sTot[e];
            g_off[e] = off;
            g_tileOfs[e] = tofs;
            off  += sTot[e];
            tofs += (sTot[e] + TILE - 1) / TILE;
        }
        g_off[EXPERTS] = off;
        g_tileOfs[EXPERTS] = tofs;
    }
    __syncthreads();
    #pragma unroll
    for (int e = 0; e < EXPERTS; ++e)
        g_blockBase[tid * EXPERTS + e] += g_off[e];
}

// ---------------- kernel C: scatter token ids ----------------
__global__ __launch_bounds__(SCAN_TPB)
void scatter_kernel(const int* __restrict__ inds, int N) {
    __shared__ int ctr[EXPERTS];
    const int cta = blockIdx.x, tid = threadIdx.x;
    if (tid < EXPERTS) ctr[tid] = g_blockBase[cta * EXPERTS + tid];
    __syncthreads();
    const int base = cta * SCAN_TOKENS;
    for (int i = tid; i < SCAN_TOKENS; i += SCAN_TPB) {
        int g = base + i;
        if (g < N) {
            int e = inds[g];
            int slot = atomicAdd(&ctr[e], 1);
            g_perm[slot] = g;
        }
    }
}

// ---------------- kernel D: pipelined TS-mode tcgen05 GEMM (cp.async gathers) ----------------
extern __shared__ char dsm[];

__global__ __launch_bounds__(GBLOCK, 2)
void gemm_kernel(const float* __restrict__ features,
                 const float* __restrict__ W,
                 const float* __restrict__ b,
                 float* __restrict__ out)
{
    char* base = (char*)(((uintptr_t)dsm + 1023) & ~(uintptr_t)1023);
    int*   sMeta = (int*)(base + OFF_META);
    int*   sTick = (int*)(base + OFF_TICK);

    const int tid = threadIdx.x;

    if (tid < 9)       sMeta[tid] = g_tileOfs[tid];
    else if (tid < 17) sMeta[tid] = g_off[tid - 9];
    else if (tid < 25) sMeta[tid] = g_cnt[tid - 17];

#if TCGEN_OK
    float* sB = (float*)(base + OFF_BIAS);
    const uint32_t sbase = smem_u32(base);
    const uint32_t mbar  = sbase + OFF_MBAR;
    const int wid   = tid >> 5;          // 0..7
    const int lane  = tid & 31;
    const int sub   = wid & 3;           // TMEM subpartition
    const int khalf = wid >> 2;          // 0: k 0..31, 1: k 32..63
    const int row   = sub * 32 + lane;   // tile row 0..127
    const uint32_t woff = (uint32_t)sub << 21;
    const int c8 = lane & 7;             // chunk within half-row
    const int g4 = lane >> 3;            // row-subgroup within gather instr

    if (tid == 0)
        asm volatile("mbarrier.init.shared.b64 [%0], 1;" :: "r"(mbar) : "memory");
    if (wid == 0)
        asm volatile("tcgen05.alloc.cta_group::1.sync.aligned.shared::cta.b32 [%0], %1;"
                     :: "r"(sbase + OFF_TMEM), "r"((uint32_t)TM_COLS) : "memory");
    __syncthreads();
    uint32_t tmem;
    asm volatile("ld.shared.b32 %0, [%1];" : "=r"(tmem) : "r"(sbase + OFF_TMEM));
    if (wid == 0)
        asm volatile("tcgen05.relinquish_alloc_permit.cta_group::1.sync.aligned;");

    const uint64_t dBH = make_desc(sbase + OFF_BH);
    const uint64_t dBL = make_desc(sbase + OFF_BL);

    const int totalTiles = sMeta[8];
    uint32_t ph = 0;
    int eCur = -1;

    // tile info (uniform per tile)
    auto tileInfo = [&](int t, int& e, int& rowStart, int& Mt) {
        e = 0;
        #pragma unroll
        for (int q = 1; q < EXPERTS; ++q) if (t >= sMeta[q]) e = q;
        int ti = t - sMeta[e];
        rowStart = sMeta[9 + e] + ti * TILE;
        Mt = min(TILE, sMeta[17 + e] - ti * TILE);
    };

    // issue cp.async gather for token-reg tokX into staging buffer pb (one group)
    auto gatherAsync = [&](int tokX, int pb) {
        const uint32_t sg = sbase + OFF_STG + (uint32_t)(pb * 8 + wid) * 4096u;
        #pragma unroll
        for (int i = 0; i < 8; ++i) {
            const int lr  = 4 * i + g4;
            const int tko = __shfl_sync(0xffffffffu, tokX, lr);
            const float* src = features + (size_t)tko * D + khalf * 32 + c8 * 4;
            const uint32_t dst = sg + (uint32_t)lr * 128u + (uint32_t)(((lr & 7) ^ c8) << 4);
            asm volatile("cp.async.cg.shared.global [%0], [%1], 16;"
                         :: "r"(dst), "l"(src) : "memory");
        }
        asm volatile("cp.async.commit_group;" ::: "memory");
    };

    auto loadB = [&](int e) {
        if (tid < 128) {
            const int j  = tid >> 1;
            const int kh = (tid & 1) * 32;
            const float* wcol = W + (size_t)e * D * D + j;
            float wv[32];
            #pragma unroll
            for (int k = 0; k < 32; ++k) wv[k] = wcol[(size_t)(kh + k) * D];
            #pragma unroll
            for (int c = 0; c < 4; ++c) {
                uint32_t hb[4], lb[4];
                #pragma unroll
                for (int p = 0; p < 4; ++p) {
                    float x0 = wv[c * 8 + 2 * p], x1 = wv[c * 8 + 2 * p + 1];
                    __nv_bfloat162 h = __floats2bfloat162_rn(x0, x1);
                    float2 hf = __bfloat1622float2(h);
                    __nv_bfloat162 l = __floats2bfloat162_rn(x0 - hf.x, x1 - hf.y);
                    hb[p] = bits2(h); lb[p] = bits2(l);
                }
                uint32_t off = (uint32_t)j * 128u + (uint32_t)(kh + c * 8) * 2u;
                uint32_t sw  = off ^ ((off >> 3) & 0x70);
                *(uint4*)(base + OFF_BH + sw) = make_uint4(hb[0], hb[1], hb[2], hb[3]);
                *(uint4*)(base + OFF_BL + sw) = make_uint4(lb[0], lb[1], lb[2], lb[3]);
            }
            if (tid < D) sB[tid] = b[e * D + tid];
        }
    };

    // ---- prologue: ticket t0 (current) ----
    if (tid == 0) *sTick = atomicAdd(&g_ticket, 1);
    __syncthreads();
    int tCur = *sTick;
    bool validCur = (tCur < totalTiles);
    int eC = 0, rsC = 0, MtC = 0, tokCur = 0;
    if (validCur) {
        tileInfo(tCur, eC, rsC, MtC);
        tokCur = g_perm[rsC + (row < MtC ? row : 0)];
        gatherAsync(tokCur, 0);
    }
    // ---- ticket t1 (next) ----
    if (tid == 0) *sTick = atomicAdd(&g_ticket, 1);
    __syncthreads();
    int tNxt = *sTick;
    bool validNxt = validCur && (tNxt < totalTiles);
    int eN = 0, rsN = 0, MtN = 0, tokNxt = 0;
    if (validNxt) {
        tileInfo(tNxt, eN, rsN, MtN);
        tokNxt = g_perm[rsN + (row < MtN ? row : 0)];
    }

    int p = 0;
    while (validCur) {
        // issue next tile's gather into the other buffer
        if (validNxt) gatherAsync(tokNxt, p ^ 1);

        // fetch ticket t+2 and its perm (latency fully hidden)
        if (tid == 0) *sTick = atomicAdd(&g_ticket, 1);
        __syncthreads();
        const int t2 = *sTick;
        const bool valid2 = validNxt && (t2 < totalTiles);
        int e2 = 0, rs2 = 0, Mt2 = 0, tok2 = 0;
        if (valid2) {
            tileInfo(t2, e2, rs2, Mt2);
            tok2 = g_perm[rs2 + (row < Mt2 ? row : 0)];
        }

        // expert weights for current tile (rare; no MMA in flight here)
        if (eC != eCur) { loadB(eC); eCur = eC; }

        // wait for CURRENT tile's gather (allow next's group outstanding)
        if (validNxt)
            asm volatile("cp.async.wait_group 1;" ::: "memory");
        else
            asm volatile("cp.async.wait_group 0;" ::: "memory");
        __syncwarp();

        // load own half-row from staging (4-phase, conflict-floor)
        char* stg = base + OFF_STG + (p * 8 + wid) * 4096;
        float4 v[8];
        #pragma unroll
        for (int c = 0; c < 8; ++c)
            v[c] = *(const float4*)(stg + lane * 128 + (((lane & 7) ^ c) << 4));

        // convert -> bf16 hi/lo, store A to TMEM
        {
            uint32_t hi[16], lo[16];
            #pragma unroll
            for (int i = 0; i < 8; ++i) {
                float4 f = v[i];
                __nv_bfloat162 h0 = __floats2bfloat162_rn(f.x, f.y);
                __nv_bfloat162 h1 = __floats2bfloat162_rn(f.z, f.w);
                float2 p0 = __bfloat1622float2(h0), p1 = __bfloat1622float2(h1);
                __nv_bfloat162 l0 = __floats2bfloat162_rn(f.x - p0.x, f.y - p0.y);
                __nv_bfloat162 l1 = __floats2bfloat162_rn(f.z - p1.x, f.w - p1.y);
                hi[2 * i] = bits2(h0); hi[2 * i + 1] = bits2(h1);
                lo[2 * i] = bits2(l0); lo[2 * i + 1] = bits2(l1);
            }
            TTM_ST_X16(tmem + TM_AHI + khalf * 16 + woff, hi);
            TTM_ST_X16(tmem + TM_ALO + khalf * 16 + woff, lo);
            asm volatile("tcgen05.wait::st.sync.aligned;" ::: "memory");
        }
        asm volatile("fence.proxy.async.shared::cta;" ::: "memory");
        asm volatile("tcgen05.fence::before_thread_sync;" ::: "memory");
        __syncthreads();                 // A in TMEM + B in smem visible

        // MMA: acc = Ah@Bh + Ah@Bl + Al@Bh
        if (wid == 0 && elect_one_pred()) {
            asm volatile("tcgen05.fence::after_thread_sync;" ::: "memory");
            const uint32_t acc = tmem + TM_ACC;
            #pragma unroll
            for (int k = 0; k < 4; ++k)
                mma_f16_ts(acc, tmem + TM_AHI + k * 8, dBH + 2 * k, IDESC_BF16, k > 0);
            #pragma unroll
            for (int k = 0; k < 4; ++k)
                mma_f16_ts(acc, tmem + TM_AHI + k * 8, dBL + 2 * k, IDESC_BF16, 1);
            #pragma unroll
            for (int k = 0; k < 4; ++k)
                mma_f16_ts(acc, tmem + TM_ALO + k * 8, dBH + 2 * k, IDESC_BF16, 1);
            asm volatile(
                "tcgen05.commit.cta_group::1.mbarrier::arrive::one.shared::cluster.b64 [%0];"
                :: "r"(mbar) : "memory");
        }

        mbar_wait(mbar, ph);
        ph ^= 1;
        asm volatile("tcgen05.fence::after_thread_sync;" ::: "memory");

        // epilogue: LDTM (lane=row) -> bias -> staging (buf p) -> coalesced STG
        uint32_t dr[32];
        LDTM_X32(dr, tmem + TM_ACC + khalf * 32 + woff);
        asm volatile("tcgen05.wait::ld.sync.aligned;" ::: "memory");

        #pragma unroll
        for (int q = 0; q < 8; ++q) {
            float4 bb = *(const float4*)(sB + khalf * 32 + q * 4);
            float4 o;
            o.x = __uint_as_float(dr[q * 4 + 0]) + bb.x;
            o.y = __uint_as_float(dr[q * 4 + 1]) + bb.y;
            o.z = __uint_as_float(dr[q * 4 + 2]) + bb.z;
            o.w = __uint_as_float(dr[q * 4 + 3]) + bb.w;
            *(uint4*)(stg + lane * 128 + (((lane & 7) ^ q) << 4)) = *(uint4*)&o;
        }
        __syncwarp();
        #pragma unroll
        for (int i = 0; i < 8; ++i) {
            const int lr  = 4 * i + g4;
            const int tko = __shfl_sync(0xffffffffu, tokCur, lr);
            if (sub * 32 + lr < MtC) {
                uint4 val = *(const uint4*)(stg + lr * 128 + (((lr & 7) ^ c8) << 4));
                *(uint4*)(out + (size_t)tko * D + khalf * 32 + c8 * 4) = val;
            }
        }
        asm volatile("tcgen05.fence::before_thread_sync;" ::: "memory");

        // rotate pipeline state
        tCur = tNxt; validCur = validNxt; eC = eN; MtC = MtN; tokCur = tokNxt;
        tNxt = t2; validNxt = valid2; eN = e2; MtN = Mt2; tokNxt = tok2;
        p ^= 1;
    }
    asm volatile("cp.async.wait_group 0;" ::: "memory");

    __syncthreads();
    if (tid == 0)
        asm volatile("mbarrier.inval.shared.b64 [%0];" :: "r"(mbar) : "memory");
    __syncthreads();
    if (wid == 0)
        asm volatile("tcgen05.dealloc.cta_group::1.sync.aligned.b32 %0, %1;"
                     :: "r"(tmem), "r"((uint32_t)TM_COLS));

#else   // !TCGEN_OK — generic-PTX fallback (compiles everywhere; sm_103a cubin runs)
    __syncthreads();
    const int totalTiles = sMeta[8];
    const int row   = ((tid >> 5) & 3) * 32 + (tid & 31);
    const int khalf = tid >> 7;
    for (;;) {
        if (tid == 0) *sTick = atomicAdd(&g_ticket, 1);
        __syncthreads();
        const int t = *sTick;
        if (t >= totalTiles) break;

        int e = 0;
        #pragma unroll
        for (int q = 1; q < EXPERTS; ++q) if (t >= sMeta[q]) e = q;
        const int ti = t - sMeta[e];
        const int rowStart = sMeta[9 + e] + ti * TILE;
        const int Mt = min(TILE, sMeta[17 + e] - ti * TILE);

        const int tok = g_perm[rowStart + (row < Mt ? row : 0)];
        const float* frow = features + (size_t)tok * D;
        float v[D];
        #pragma unroll
        for (int k = 0; k < D; ++k) v[k] = frow[k];

        if (row < Mt) {
            const float* We = W + (size_t)e * D * D;
            for (int j = khalf * 32; j < khalf * 32 + 32; ++j) {
                float s = b[e * D + j];
                #pragma unroll 16
                for (int k = 0; k < D; ++k) s = fmaf(v[k], We[(size_t)k * D + j], s);
                out[(size_t)tok * D + j] = s;
            }
        }
        __syncthreads();
    }
#endif
}

// ---------------- launch ----------------
extern "C" void kernel_launch(void* const* d_in, const int* in_sizes, int n_in,
                              void* d_out, int out_size) {
    const float* features = (const float*)d_in[0];
    const int*   inds     = (const int*)d_in[1];
    const float* W        = (const float*)d_in[2];
    const float* b        = (const float*)d_in[3];
    float*       out      = (float*)d_out;

    int N = in_sizes[0] / D;

    (void)cudaFuncSetAttribute(gemm_kernel,
                               cudaFuncAttributeMaxDynamicSharedMemorySize,
                               SMEM_SZ);

    int nScan = (N + SCAN_TOKENS - 1) / SCAN_TOKENS;
    count_kernel<<<nScan, SCAN_TPB>>>(inds, N);
    scan_kernel<<<1, NUM_SCAN_CTAS>>>();
    scatter_kernel<<<nScan, SCAN_TPB>>>(inds, N);
    gemm_kernel<<<NCTA_GEMM, GBLOCK, SMEM_SZ>>>(features, W, b, out);
}